// round 11
// baseline (speedup 1.0000x reference)
#include <cuda_runtime.h>
#include <cuda_bf16.h>
#include <cuda_fp16.h>

#define N_NODES 100000
#define N_EDGES 1600000
#define IN_F 128
#define OUT_F 32
#define HEADS 2
#define NHF 64  // HEADS*OUT_F
#define SCAN_BLK 1024
#define N_SCAN_BLKS ((N_NODES + SCAN_BLK - 1) / SCAN_BLK)  // 98
#define GEMM_BLKS ((N_NODES + 63) / 64)                     // 1563
#define SCAT_BLKS (N_EDGES / 4 / 128)                       // 3125

typedef unsigned long long u64;

// ---- packed f32x2 helpers (Blackwell FFMA2 path; ptxas won't auto-fuse) ----
__device__ __forceinline__ u64 pack2(float a, float b) {
    u64 r; asm("mov.b64 %0, {%1, %2};" : "=l"(r) : "f"(a), "f"(b)); return r;
}
__device__ __forceinline__ void ffma2(u64& d, u64 a, u64 b) {
    asm("fma.rn.f32x2 %0, %1, %2, %3;" : "=l"(d) : "l"(a), "l"(b), "l"(d));
}
__device__ __forceinline__ float2 unpack2(u64 v) {
    float2 f; asm("mov.b64 {%0, %1}, %2;" : "=f"(f.x), "=f"(f.y) : "l"(v)); return f;
}

// ---- scratch (device globals; zero-initialized at module load) ----
__device__ __half g_feat_h[N_NODES * NHF];  // fp16 feat for the agg gathers
__device__ float g_el[N_NODES * HEADS];
__device__ float g_er[N_NODES * HEADS];
__device__ float g_a[N_NODES];
__device__ float g_b[N_NODES];
__device__ float g_vfold[NHF];
__device__ float g_cfold;
// CSR-by-dst scratch. INVARIANT: g_deg all-zero at entry (zero-init at load;
// k_scan3 re-zeroes each run). g_ticket reset by k_scan1's last block.
__device__ int g_deg[N_NODES];
__device__ int g_cur[N_NODES];
__device__ int g_off[N_NODES + 1];
__device__ int g_srcs[N_EDGES];
__device__ int g_blksum[N_SCAN_BLKS];
__device__ int g_ticket;

// ---- histogram of dst (4 edges/thread) + MLP fold in block 0 ----
__global__ void k_hist(const int* __restrict__ dst,
                       const float* __restrict__ W1, const float* __restrict__ b1,
                       const float* __restrict__ W2, const float* __restrict__ b2) {
    if (blockIdx.x == 0) {
        int t = threadIdx.x;
        if (t < NHF) {
            float v = 0.f;
            #pragma unroll
            for (int j = 0; j < OUT_F; ++j) v += W1[t * OUT_F + j] * W2[j];
            g_vfold[t] = v;
        }
        if (t == 0) {
            float c = b2[0];
            for (int j = 0; j < OUT_F; ++j) c += b1[j] * W2[j];
            g_cfold = c;
        }
    }
    int i = blockIdx.x * blockDim.x + threadIdx.x;
    if (i * 4 >= N_EDGES) return;
    int4 d = *(const int4*)&dst[i * 4];
    atomicAdd(&g_deg[d.x], 1);
    atomicAdd(&g_deg[d.y], 1);
    atomicAdd(&g_deg[d.z], 1);
    atomicAdd(&g_deg[d.w], 1);
}

// ---- scan phase 1+2 fused: per-block sums; last block scans the 98 sums ----
__global__ void k_scan1() {
    __shared__ int s[SCAN_BLK];
    __shared__ int is_last;
    int i = blockIdx.x * SCAN_BLK + threadIdx.x;
    s[threadIdx.x] = (i < N_NODES) ? g_deg[i] : 0;
    __syncthreads();
    #pragma unroll
    for (int off = SCAN_BLK / 2; off > 0; off >>= 1) {
        if (threadIdx.x < off) s[threadIdx.x] += s[threadIdx.x + off];
        __syncthreads();
    }
    if (threadIdx.x == 0) {
        g_blksum[blockIdx.x] = s[0];
        __threadfence();
        int t = atomicAdd(&g_ticket, 1);
        is_last = (t == gridDim.x - 1);
    }
    __syncthreads();
    if (!is_last) return;
    __shared__ int s2[128];
    int t = threadIdx.x;
    if (t < 128) {
        int v = (t < N_SCAN_BLKS) ? g_blksum[t] : 0;
        s2[t] = v;
        __syncthreads();
        #pragma unroll
        for (int off = 1; off < 128; off <<= 1) {
            int u = (t >= off) ? s2[t - off] : 0;
            __syncthreads();
            s2[t] += u;
            __syncthreads();
        }
        if (t < N_SCAN_BLKS) g_blksum[t] = s2[t] - v;  // exclusive prefix
        if (t == 127) g_off[N_NODES] = s2[127];
        if (t == 0) g_ticket = 0;                      // restore invariant
    } else {
        __syncthreads();
        #pragma unroll
        for (int off = 1; off < 128; off <<= 1) { __syncthreads(); __syncthreads(); }
    }
}

// ---- scan phase 3: in-block exclusive scan + block offset; re-zero g_deg ----
__global__ void k_scan3() {
    __shared__ int s[SCAN_BLK];
    int i = blockIdx.x * SCAN_BLK + threadIdx.x;
    int v = (i < N_NODES) ? g_deg[i] : 0;
    s[threadIdx.x] = v;
    __syncthreads();
    #pragma unroll
    for (int off = 1; off < SCAN_BLK; off <<= 1) {
        int u = (threadIdx.x >= off) ? s[threadIdx.x - off] : 0;
        __syncthreads();
        s[threadIdx.x] += u;
        __syncthreads();
    }
    if (i < N_NODES) {
        int excl = g_blksum[blockIdx.x] + s[threadIdx.x] - v;
        g_off[i] = excl;
        g_cur[i] = excl;
        g_deg[i] = 0;
    }
}

// ---- fused: GEMM-FFMA2 (blocks [0,GEMM_BLKS)) || scatter (rest) ----
// Microtile 4 rows x 8 cols per thread; accumulators are packed f32x2 so
// every fma.rn.f32x2 retires 2 FMAs (FFMA-3reg is half-rate on B300).
__global__ void k_scatter_gemm(const int* __restrict__ src, const int* __restrict__ dst,
                               const float* __restrict__ x, const float* __restrict__ W,
                               const float* __restrict__ attn_l,
                               const float* __restrict__ attn_r) {
    __shared__ float Xs[64][68];  // [k][m]; stride 272B keeps float4 alignment
    __shared__ float Ws[64][64];  // [k][n]
    if (blockIdx.x >= GEMM_BLKS) {
        int i = (blockIdx.x - GEMM_BLKS) * 128 + threadIdx.x;
        int4 s = *(const int4*)&src[i * 4];
        int4 d = *(const int4*)&dst[i * 4];
        g_srcs[atomicAdd(&g_cur[d.x], 1)] = s.x;
        g_srcs[atomicAdd(&g_cur[d.y], 1)] = s.y;
        g_srcs[atomicAdd(&g_cur[d.z], 1)] = s.z;
        g_srcs[atomicAdd(&g_cur[d.w], 1)] = s.w;
        return;
    }
    const int block_row = blockIdx.x * 64;
    const int t = threadIdx.x;     // 128 threads
    const int tx = t & 7;          // col group: 8 cols (tx*8..tx*8+7)
    const int ty = t >> 3;         // row group: 4 rows (ty*4..ty*4+3)

    u64 acc[4][4];                 // [row][colpair] packed f32x2
    #pragma unroll
    for (int r = 0; r < 4; ++r)
        #pragma unroll
        for (int p = 0; p < 4; ++p) acc[r][p] = 0ull;

    for (int kt = 0; kt < 2; ++kt) {
        #pragma unroll
        for (int i = t; i < 64 * 16; i += 128) {
            int row = i >> 4, kq = i & 15;
            int gr = block_row + row;
            float4 v = make_float4(0.f, 0.f, 0.f, 0.f);
            if (gr < N_NODES)
                v = *(const float4*)&x[gr * IN_F + kt * 64 + kq * 4];
            Xs[kq * 4 + 0][row] = v.x;
            Xs[kq * 4 + 1][row] = v.y;
            Xs[kq * 4 + 2][row] = v.z;
            Xs[kq * 4 + 3][row] = v.w;
        }
        #pragma unroll
        for (int i = t; i < 64 * 16; i += 128) {
            int kk = i >> 4, nq = i & 15;
            *(float4*)&Ws[kk][nq * 4] =
                *(const float4*)&W[(kt * 64 + kk) * NHF + nq * 4];
        }
        __syncthreads();
        #pragma unroll 8
        for (int k = 0; k < 64; ++k) {
            // W pairs come free as 64-bit lanes of a 128-bit smem load
            ulonglong2 wa = *(const ulonglong2*)&Ws[k][tx * 8];
            ulonglong2 wb = *(const ulonglong2*)&Ws[k][tx * 8 + 4];
            float4 xv = *(const float4*)&Xs[k][ty * 4];
            u64 xx0 = pack2(xv.x, xv.x);
            u64 xx1 = pack2(xv.y, xv.y);
            u64 xx2 = pack2(xv.z, xv.z);
            u64 xx3 = pack2(xv.w, xv.w);
            ffma2(acc[0][0], xx0, wa.x); ffma2(acc[0][1], xx0, wa.y);
            ffma2(acc[0][2], xx0, wb.x); ffma2(acc[0][3], xx0, wb.y);
            ffma2(acc[1][0], xx1, wa.x); ffma2(acc[1][1], xx1, wa.y);
            ffma2(acc[1][2], xx1, wb.x); ffma2(acc[1][3], xx1, wb.y);
            ffma2(acc[2][0], xx2, wa.x); ffma2(acc[2][1], xx2, wa.y);
            ffma2(acc[2][2], xx2, wb.x); ffma2(acc[2][3], xx2, wb.y);
            ffma2(acc[3][0], xx3, wa.x); ffma2(acc[3][1], xx3, wa.y);
            ffma2(acc[3][2], xx3, wb.x); ffma2(acc[3][3], xx3, wb.y);
        }
        __syncthreads();
    }

    // epilogue: fp16 feat store + el/er attention dots
    float4 al0 = *(const float4*)&attn_l[tx * 8];
    float4 al1 = *(const float4*)&attn_l[tx * 8 + 4];
    float4 ar0 = *(const float4*)&attn_r[tx * 8];
    float4 ar1 = *(const float4*)&attn_r[tx * 8 + 4];
    float pel[4], per[4];
    #pragma unroll
    for (int r = 0; r < 4; ++r) {
        float2 f0 = unpack2(acc[r][0]);
        float2 f1 = unpack2(acc[r][1]);
        float2 f2 = unpack2(acc[r][2]);
        float2 f3 = unpack2(acc[r][3]);
        int gr = block_row + ty * 4 + r;
        if (gr < N_NODES) {
            __half2 h[4];
            h[0] = __floats2half2_rn(f0.x, f0.y);
            h[1] = __floats2half2_rn(f1.x, f1.y);
            h[2] = __floats2half2_rn(f2.x, f2.y);
            h[3] = __floats2half2_rn(f3.x, f3.y);
            *(float4*)&g_feat_h[gr * NHF + tx * 8] = *(float4*)h;  // 1 STG.128
        }
        pel[r] = f0.x * al0.x + f0.y * al0.y + f1.x * al0.z + f1.y * al0.w
               + f2.x * al1.x + f2.y * al1.y + f3.x * al1.z + f3.y * al1.w;
        per[r] = f0.x * ar0.x + f0.y * ar0.y + f1.x * ar0.z + f1.y * ar0.w
               + f2.x * ar1.x + f2.y * ar1.y + f3.x * ar1.z + f3.y * ar1.w;
    }
    // reduce across tx within each head: tx {0..3} = head0 cols, {4..7} = head1
    #pragma unroll
    for (int o = 1; o < 4; o <<= 1) {
        #pragma unroll
        for (int r = 0; r < 4; ++r) {
            pel[r] += __shfl_xor_sync(0xFFFFFFFFu, pel[r], o);
            per[r] += __shfl_xor_sync(0xFFFFFFFFu, per[r], o);
        }
    }
    if ((tx & 3) == 0) {
        int h = tx >> 2;   // tx==0 -> head0, tx==4 -> head1
        #pragma unroll
        for (int r = 0; r < 4; ++r) {
            int gr = block_row + ty * 4 + r;
            if (gr < N_NODES) {
                g_el[gr * 2 + h] = pel[r];
                g_er[gr * 2 + h] = per[r];
            }
        }
    }
}

// ---- fused per-dst-node: softmax + aggregation + epilogue (warp per node) ----
__global__ void k_agg(const float* __restrict__ bias_gat) {
    int warp = (blockIdx.x * blockDim.x + threadIdx.x) >> 5;
    int lane = threadIdx.x & 31;
    if (warp >= N_NODES) return;
    const int n = warp;
    const int beg = g_off[n];
    const int end = g_off[n + 1];

    const float2 erd = *(const float2*)&g_er[n * 2];
    float2 acc = make_float2(0.f, 0.f);
    float den0 = 0.f, den1 = 0.f;

    for (int base = beg; base < end; base += 32) {
        const int cnt = min(32, end - base);
        int s = 0;
        float ex0 = 0.f, ex1 = 0.f;
        if (lane < cnt) {
            s = g_srcs[base + lane];
            float2 els = *(const float2*)&g_el[s * 2];
            float v0 = els.x + erd.x;
            float v1 = els.y + erd.y;
            v0 = v0 > 0.f ? v0 : 0.2f * v0;
            v1 = v1 > 0.f ? v1 : 0.2f * v1;
            ex0 = __expf(v0);
            ex1 = __expf(v1);
        }
        for (int j = 0; j < cnt; ++j) {
            int sj = __shfl_sync(0xFFFFFFFFu, s, j);
            float e0 = __shfl_sync(0xFFFFFFFFu, ex0, j);
            float e1 = __shfl_sync(0xFFFFFFFFu, ex1, j);
            __half2 fh = *(const __half2*)&g_feat_h[sj * NHF + 2 * lane];
            float2 f = __half22float2(fh);
            float w = (lane < 16) ? e0 : e1;
            acc.x = fmaf(w, f.x, acc.x);
            acc.y = fmaf(w, f.y, acc.y);
            den0 += e0;
            den1 += e1;
        }
    }

    float inv0 = (den0 > 0.f) ? 1.f / den0 : 0.f;
    float inv1 = (den1 > 0.f) ? 1.f / den1 : 0.f;
    float myinv = (lane < 16) ? inv0 : inv1;
    float rx = acc.x * myinv;
    float ry = acc.y * myinv;
    float ox = __shfl_xor_sync(0xFFFFFFFFu, rx, 16);
    float oy = __shfl_xor_sync(0xFFFFFFFFu, ry, 16);
    int c0 = 2 * (lane & 15);
    float2 bh0 = *(const float2*)&bias_gat[c0];
    float2 bh1 = *(const float2*)&bias_gat[32 + c0];
    float h0 = fmaxf(0.5f * (rx + ox + bh0.x + bh1.x), 0.f);
    float h1 = fmaxf(0.5f * (ry + oy + bh0.y + bh1.y), 0.f);
    float2 va = *(const float2*)&g_vfold[c0];
    float2 vb = *(const float2*)&g_vfold[32 + c0];
    float av = h0 * va.x + h1 * va.y;
    float bv = h0 * vb.x + h1 * vb.y;
    #pragma unroll
    for (int o = 1; o < 16; o <<= 1) {
        av += __shfl_xor_sync(0xFFFFFFFFu, av, o);
        bv += __shfl_xor_sync(0xFFFFFFFFu, bv, o);
    }
    if (lane == 0) { g_a[n] = av; g_b[n] = bv; }
}

// ---- per-edge final score (4 edges per thread) ----
__global__ void k_edge_score(const int* __restrict__ src, const int* __restrict__ dst,
                             float* __restrict__ out) {
    int i = blockIdx.x * blockDim.x + threadIdx.x;
    if (i * 4 >= N_EDGES) return;
    int4 s = *(const int4*)&src[i * 4];
    int4 d = *(const int4*)&dst[i * 4];
    float c = g_cfold;
    float4 r;
    r.x = g_a[s.x] + g_b[d.x] + c;
    r.y = g_a[s.y] + g_b[d.y] + c;
    r.z = g_a[s.z] + g_b[d.z] + c;
    r.w = g_a[s.w] + g_b[d.w] + c;
    *(float4*)&out[i * 4] = r;
}

extern "C" void kernel_launch(void* const* d_in, const int* in_sizes, int n_in,
                              void* d_out, int out_size) {
    const float* x       = (const float*)d_in[0];
    const float* W       = (const float*)d_in[1];
    const float* attn_l  = (const float*)d_in[2];
    const float* attn_r  = (const float*)d_in[3];
    const float* bias_gat= (const float*)d_in[4];
    const float* W1      = (const float*)d_in[5];
    const float* b1      = (const float*)d_in[6];
    const float* W2      = (const float*)d_in[7];
    const float* b2      = (const float*)d_in[8];
    const int*   src     = (const int*)d_in[9];
    const int*   dst     = (const int*)d_in[10];
    float* out = (float*)d_out;

    k_hist<<<(N_EDGES / 4 + 255) / 256, 256>>>(dst, W1, b1, W2, b2);
    k_scan1<<<N_SCAN_BLKS, SCAN_BLK>>>();
    k_scan3<<<N_SCAN_BLKS, SCAN_BLK>>>();
    k_scatter_gemm<<<GEMM_BLKS + SCAT_BLKS, 128>>>(src, dst, x, W, attn_l, attn_r);
    k_agg<<<(N_NODES * 32 + 255) / 256, 256>>>(bias_gat);
    k_edge_score<<<(N_EDGES / 4 + 255) / 256, 256>>>(src, dst, out);
}

// round 12
// speedup vs baseline: 1.0063x; 1.0063x over previous
#include <cuda_runtime.h>
#include <cuda_bf16.h>
#include <cuda_fp16.h>

#define N_NODES 100000
#define N_EDGES 1600000
#define IN_F 128
#define OUT_F 32
#define HEADS 2
#define NHF 64  // HEADS*OUT_F
#define SCAN_BLK 1024
#define N_SCAN_BLKS ((N_NODES + SCAN_BLK - 1) / SCAN_BLK)  // 98
#define GEMM_TILES ((N_NODES + 63) / 64)   // 1563
#define GA_TILES 521                        // phase-1 GEMM tiles (1563 = 3*521)
#define GB_TILES (GEMM_TILES - GA_TILES)    // 1042
#define HIST_BLKS 1563                      // 3 per group of 4 in phase 1
#define SCAT_BLKS 3125                      // 3125*128 int4-groups = 1.6M edges
#define SCAT_GROUPS 1042                    // ceil(3125/3)

// ---- scratch (device globals; zero-initialized at module load) ----
__device__ __half g_feat_h[N_NODES * NHF];  // fp16 feat for the agg gathers
__device__ float g_el[N_NODES * HEADS];
__device__ float g_er[N_NODES * HEADS];
__device__ float g_a[N_NODES];
__device__ float g_b[N_NODES];
__device__ float g_vfold[NHF];
__device__ float g_cfold;
// CSR-by-dst scratch. INVARIANT: g_deg all-zero at entry (zero-init at load;
// k_scan3 re-zeroes each run). g_ticket reset by k_scan1's last block.
__device__ int g_deg[N_NODES];
__device__ int g_cur[N_NODES];
__device__ int g_off[N_NODES + 1];
__device__ int g_srcs[N_EDGES];
__device__ int g_blksum[N_SCAN_BLKS];
__device__ int g_ticket;

// ==== R10 scalar GEMM tile body (known-good 4-col x 8-row microtile) ====
__device__ __forceinline__ void gemm_tile(int tile, int t,
                                          const float* __restrict__ x,
                                          const float* __restrict__ W,
                                          const float* __restrict__ attn_l,
                                          const float* __restrict__ attn_r,
                                          float (*Xs)[68], float (*Ws)[64]) {
    const int block_row = tile * 64;
    const int tx = t & 15;             // col group: 4 cols
    const int ty = t >> 4;             // row group: 8 rows
    float acc[8][4];
    #pragma unroll
    for (int r = 0; r < 8; ++r)
        #pragma unroll
        for (int c = 0; c < 4; ++c) acc[r][c] = 0.f;

    for (int kt = 0; kt < 2; ++kt) {
        #pragma unroll
        for (int i = t; i < 64 * 16; i += 128) {
            int row = i >> 4, kq = i & 15;
            int gr = block_row + row;
            float4 v = make_float4(0.f, 0.f, 0.f, 0.f);
            if (gr < N_NODES)
                v = *(const float4*)&x[gr * IN_F + kt * 64 + kq * 4];
            Xs[kq * 4 + 0][row] = v.x;
            Xs[kq * 4 + 1][row] = v.y;
            Xs[kq * 4 + 2][row] = v.z;
            Xs[kq * 4 + 3][row] = v.w;
        }
        #pragma unroll
        for (int i = t; i < 64 * 16; i += 128) {
            int kk = i >> 4, nq = i & 15;
            *(float4*)&Ws[kk][nq * 4] =
                *(const float4*)&W[(kt * 64 + kk) * NHF + nq * 4];
        }
        __syncthreads();
        #pragma unroll 16
        for (int k = 0; k < 64; ++k) {
            float4 wv = *(const float4*)&Ws[k][tx * 4];
            float4 x0 = *(const float4*)&Xs[k][ty * 8];
            float4 x1 = *(const float4*)&Xs[k][ty * 8 + 4];
            float xr[8] = {x0.x, x0.y, x0.z, x0.w, x1.x, x1.y, x1.z, x1.w};
            #pragma unroll
            for (int r = 0; r < 8; ++r) {
                acc[r][0] += xr[r] * wv.x;
                acc[r][1] += xr[r] * wv.y;
                acc[r][2] += xr[r] * wv.z;
                acc[r][3] += xr[r] * wv.w;
            }
        }
        __syncthreads();
    }
    // epilogue: fp16 feat store + el/er attention dot partials
    float4 al = *(const float4*)&attn_l[tx * 4];
    float4 ar = *(const float4*)&attn_r[tx * 4];
    float pel[8], per[8];
    #pragma unroll
    for (int r = 0; r < 8; ++r) {
        int gr = block_row + ty * 8 + r;
        if (gr < N_NODES) {
            __half2 h01 = __floats2half2_rn(acc[r][0], acc[r][1]);
            __half2 h23 = __floats2half2_rn(acc[r][2], acc[r][3]);
            *(__half2*)&g_feat_h[gr * NHF + tx * 4] = h01;
            *(__half2*)&g_feat_h[gr * NHF + tx * 4 + 2] = h23;
        }
        pel[r] = acc[r][0] * al.x + acc[r][1] * al.y + acc[r][2] * al.z + acc[r][3] * al.w;
        per[r] = acc[r][0] * ar.x + acc[r][1] * ar.y + acc[r][2] * ar.z + acc[r][3] * ar.w;
    }
    #pragma unroll
    for (int o = 1; o < 8; o <<= 1) {
        #pragma unroll
        for (int r = 0; r < 8; ++r) {
            pel[r] += __shfl_xor_sync(0xFFFFFFFFu, pel[r], o);
            per[r] += __shfl_xor_sync(0xFFFFFFFFu, per[r], o);
        }
    }
    if ((tx & 7) == 0) {
        int h = tx >> 3;
        #pragma unroll
        for (int r = 0; r < 8; ++r) {
            int gr = block_row + ty * 8 + r;
            if (gr < N_NODES) {
                g_el[gr * 2 + h] = pel[r];
                g_er[gr * 2 + h] = per[r];
            }
        }
    }
}

// ---- phase 1: hist (3 of every 4 blocks) interleaved with GEMM-A (1 of 4) ----
__global__ void k_phase1(const int* __restrict__ dst,
                         const float* __restrict__ x, const float* __restrict__ W,
                         const float* __restrict__ attn_l, const float* __restrict__ attn_r,
                         const float* __restrict__ W1, const float* __restrict__ b1,
                         const float* __restrict__ W2, const float* __restrict__ b2) {
    __shared__ float Xs[64][68];
    __shared__ float Ws[64][64];
    const int q = blockIdx.x >> 2, r = blockIdx.x & 3;
    const int t = threadIdx.x;
    if (r == 3) {               // GEMM-A tile q (q < GA_TILES)
        gemm_tile(q, t, x, W, attn_l, attn_r, Xs, Ws);
        return;
    }
    const int h = q * 3 + r;    // hist block 0..1562
    if (h == 0) {               // MLP fold piggybacked on the first hist block
        if (t < NHF) {
            float v = 0.f;
            #pragma unroll
            for (int j = 0; j < OUT_F; ++j) v += W1[t * OUT_F + j] * W2[j];
            g_vfold[t] = v;
        }
        if (t == 0) {
            float c = b2[0];
            for (int j = 0; j < OUT_F; ++j) c += b1[j] * W2[j];
            g_cfold = c;
        }
    }
    // 256 int4-groups per hist block (two strided groups per thread)
    #pragma unroll
    for (int rep = 0; rep < 2; ++rep) {
        int g = h * 256 + rep * 128 + t;
        if (g * 4 < N_EDGES) {
            int4 d = *(const int4*)&dst[g * 4];
            atomicAdd(&g_deg[d.x], 1);
            atomicAdd(&g_deg[d.y], 1);
            atomicAdd(&g_deg[d.z], 1);
            atomicAdd(&g_deg[d.w], 1);
        }
    }
}

// ---- scan phase 1+2 fused: per-block sums; last block scans the 98 sums ----
__global__ void k_scan1() {
    __shared__ int s[SCAN_BLK];
    __shared__ int is_last;
    int i = blockIdx.x * SCAN_BLK + threadIdx.x;
    s[threadIdx.x] = (i < N_NODES) ? g_deg[i] : 0;
    __syncthreads();
    #pragma unroll
    for (int off = SCAN_BLK / 2; off > 0; off >>= 1) {
        if (threadIdx.x < off) s[threadIdx.x] += s[threadIdx.x + off];
        __syncthreads();
    }
    if (threadIdx.x == 0) {
        g_blksum[blockIdx.x] = s[0];
        __threadfence();
        int t = atomicAdd(&g_ticket, 1);
        is_last = (t == gridDim.x - 1);
    }
    __syncthreads();
    if (!is_last) return;
    __shared__ int s2[128];
    int t = threadIdx.x;
    if (t < 128) {
        int v = (t < N_SCAN_BLKS) ? g_blksum[t] : 0;
        s2[t] = v;
        __syncthreads();
        #pragma unroll
        for (int off = 1; off < 128; off <<= 1) {
            int u = (t >= off) ? s2[t - off] : 0;
            __syncthreads();
            s2[t] += u;
            __syncthreads();
        }
        if (t < N_SCAN_BLKS) g_blksum[t] = s2[t] - v;  // exclusive prefix
        if (t == 127) g_off[N_NODES] = s2[127];
        if (t == 0) g_ticket = 0;                      // restore invariant
    } else {
        __syncthreads();
        #pragma unroll
        for (int off = 1; off < 128; off <<= 1) { __syncthreads(); __syncthreads(); }
    }
}

// ---- scan phase 3: in-block exclusive scan + block offset; re-zero g_deg ----
__global__ void k_scan3() {
    __shared__ int s[SCAN_BLK];
    int i = blockIdx.x * SCAN_BLK + threadIdx.x;
    int v = (i < N_NODES) ? g_deg[i] : 0;
    s[threadIdx.x] = v;
    __syncthreads();
    #pragma unroll
    for (int off = 1; off < SCAN_BLK; off <<= 1) {
        int u = (threadIdx.x >= off) ? s[threadIdx.x - off] : 0;
        __syncthreads();
        s[threadIdx.x] += u;
        __syncthreads();
    }
    if (i < N_NODES) {
        int excl = g_blksum[blockIdx.x] + s[threadIdx.x] - v;
        g_off[i] = excl;
        g_cur[i] = excl;
        g_deg[i] = 0;
    }
}

// ---- phase 4: scatter (3 of every 4 blocks) interleaved with GEMM-B ----
__global__ void k_phase4(const int* __restrict__ src, const int* __restrict__ dst,
                         const float* __restrict__ x, const float* __restrict__ W,
                         const float* __restrict__ attn_l,
                         const float* __restrict__ attn_r) {
    __shared__ float Xs[64][68];
    __shared__ float Ws[64][64];
    const int q = blockIdx.x >> 2, r = blockIdx.x & 3;
    const int t = threadIdx.x;
    if (r == 3) {               // GEMM-B tile
        gemm_tile(GA_TILES + q, t, x, W, attn_l, attn_r, Xs, Ws);
        return;
    }
    const int sb = q * 3 + r;   // scatter block 0..3124 (one pad group)
    if (sb >= SCAT_BLKS) return;
    int i = sb * 128 + t;       // int4-group index; 3125*128 = 400000 exact
    int4 s = *(const int4*)&src[i * 4];
    int4 d = *(const int4*)&dst[i * 4];
    g_srcs[atomicAdd(&g_cur[d.x], 1)] = s.x;
    g_srcs[atomicAdd(&g_cur[d.y], 1)] = s.y;
    g_srcs[atomicAdd(&g_cur[d.z], 1)] = s.z;
    g_srcs[atomicAdd(&g_cur[d.w], 1)] = s.w;
}

// ---- fused per-dst-node: softmax + aggregation + epilogue (warp per node) ----
__global__ void k_agg(const float* __restrict__ bias_gat) {
    int warp = (blockIdx.x * blockDim.x + threadIdx.x) >> 5;
    int lane = threadIdx.x & 31;
    if (warp >= N_NODES) return;
    const int n = warp;
    const int beg = g_off[n];
    const int end = g_off[n + 1];

    const float2 erd = *(const float2*)&g_er[n * 2];
    float2 acc = make_float2(0.f, 0.f);
    float den0 = 0.f, den1 = 0.f;

    for (int base = beg; base < end; base += 32) {
        const int cnt = min(32, end - base);
        int s = 0;
        float ex0 = 0.f, ex1 = 0.f;
        if (lane < cnt) {
            s = g_srcs[base + lane];
            float2 els = *(const float2*)&g_el[s * 2];
            float v0 = els.x + erd.x;
            float v1 = els.y + erd.y;
            v0 = v0 > 0.f ? v0 : 0.2f * v0;
            v1 = v1 > 0.f ? v1 : 0.2f * v1;
            ex0 = __expf(v0);
            ex1 = __expf(v1);
        }
        for (int j = 0; j < cnt; ++j) {
            int sj = __shfl_sync(0xFFFFFFFFu, s, j);
            float e0 = __shfl_sync(0xFFFFFFFFu, ex0, j);
            float e1 = __shfl_sync(0xFFFFFFFFu, ex1, j);
            __half2 fh = *(const __half2*)&g_feat_h[sj * NHF + 2 * lane];
            float2 f = __half22float2(fh);
            float w = (lane < 16) ? e0 : e1;
            acc.x = fmaf(w, f.x, acc.x);
            acc.y = fmaf(w, f.y, acc.y);
            den0 += e0;
            den1 += e1;
        }
    }

    float inv0 = (den0 > 0.f) ? 1.f / den0 : 0.f;
    float inv1 = (den1 > 0.f) ? 1.f / den1 : 0.f;
    float myinv = (lane < 16) ? inv0 : inv1;
    float rx = acc.x * myinv;
    float ry = acc.y * myinv;
    float ox = __shfl_xor_sync(0xFFFFFFFFu, rx, 16);
    float oy = __shfl_xor_sync(0xFFFFFFFFu, ry, 16);
    int c0 = 2 * (lane & 15);
    float2 bh0 = *(const float2*)&bias_gat[c0];
    float2 bh1 = *(const float2*)&bias_gat[32 + c0];
    float h0 = fmaxf(0.5f * (rx + ox + bh0.x + bh1.x), 0.f);
    float h1 = fmaxf(0.5f * (ry + oy + bh0.y + bh1.y), 0.f);
    float2 va = *(const float2*)&g_vfold[c0];
    float2 vb = *(const float2*)&g_vfold[32 + c0];
    float av = h0 * va.x + h1 * va.y;
    float bv = h0 * vb.x + h1 * vb.y;
    #pragma unroll
    for (int o = 1; o < 16; o <<= 1) {
        av += __shfl_xor_sync(0xFFFFFFFFu, av, o);
        bv += __shfl_xor_sync(0xFFFFFFFFu, bv, o);
    }
    if (lane == 0) { g_a[n] = av; g_b[n] = bv; }
}

// ---- per-edge final score (4 edges per thread) ----
__global__ void k_edge_score(const int* __restrict__ src, const int* __restrict__ dst,
                             float* __restrict__ out) {
    int i = blockIdx.x * blockDim.x + threadIdx.x;
    if (i * 4 >= N_EDGES) return;
    int4 s = *(const int4*)&src[i * 4];
    int4 d = *(const int4*)&dst[i * 4];
    float c = g_cfold;
    float4 r;
    r.x = g_a[s.x] + g_b[d.x] + c;
    r.y = g_a[s.y] + g_b[d.y] + c;
    r.z = g_a[s.z] + g_b[d.z] + c;
    r.w = g_a[s.w] + g_b[d.w] + c;
    *(float4*)&out[i * 4] = r;
}

extern "C" void kernel_launch(void* const* d_in, const int* in_sizes, int n_in,
                              void* d_out, int out_size) {
    const float* x       = (const float*)d_in[0];
    const float* W       = (const float*)d_in[1];
    const float* attn_l  = (const float*)d_in[2];
    const float* attn_r  = (const float*)d_in[3];
    const float* bias_gat= (const float*)d_in[4];
    const float* W1      = (const float*)d_in[5];
    const float* b1      = (const float*)d_in[6];
    const float* W2      = (const float*)d_in[7];
    const float* b2      = (const float*)d_in[8];
    const int*   src     = (const int*)d_in[9];
    const int*   dst     = (const int*)d_in[10];
    float* out = (float*)d_out;

    k_phase1<<<GA_TILES * 4, 128>>>(dst, x, W, attn_l, attn_r, W1, b1, W2, b2);
    k_scan1<<<N_SCAN_BLKS, SCAN_BLK>>>();
    k_scan3<<<N_SCAN_BLKS, SCAN_BLK>>>();
    k_phase4<<<SCAT_GROUPS * 4, 128>>>(src, dst, x, W, attn_l, attn_r);
    k_agg<<<(N_NODES * 32 + 255) / 256, 256>>>(bias_gat);
    k_edge_score<<<(N_EDGES / 4 + 255) / 256, 256>>>(src, dst, out);
}

// round 14
// speedup vs baseline: 1.1318x; 1.1247x over previous
#include <cuda_runtime.h>
#include <cuda_bf16.h>
#include <cuda_fp16.h>
#include <cstdint>

#define N_NODES 100000
#define N_EDGES 1600000
#define IN_F 128
#define OUT_F 32
#define HEADS 2
#define NHF 64  // HEADS*OUT_F
#define SCAN_BLK 1024
#define N_SCAN_BLKS ((N_NODES + SCAN_BLK - 1) / SCAN_BLK)  // 98
#define GEMM_BLKS ((N_NODES + 63) / 64)                     // 1563

// ---- scratch (device globals; zero-initialized at module load) ----
__device__ __half g_feat_h[N_NODES * NHF];  // fp16 feat for the agg gathers
__device__ __half g_wt_h[72 * IN_F];        // B^T fp16: [n][k]; rows 64-67 = wl/wr folds
__device__ float g_el[N_NODES * HEADS];
__device__ float g_er[N_NODES * HEADS];
__device__ float g_a[N_NODES];
__device__ float g_b[N_NODES];
__device__ float g_vfold[NHF];
__device__ float g_cfold;
// CSR-by-dst scratch. INVARIANT: g_deg all-zero at entry (zero-init at load;
// k_scan3 re-zeroes each run). g_ticket reset by k_scan1's last block.
__device__ int g_deg[N_NODES];
__device__ int g_cur[N_NODES];
__device__ int g_off[N_NODES + 1];
__device__ int g_srcs[N_EDGES];
__device__ int g_blksum[N_SCAN_BLKS];
__device__ int g_ticket;

// ---- hist (4 edges/thread) + block 0: MLP fold, W transpose+fold to fp16 ----
__global__ void k_hist(const int* __restrict__ dst,
                       const float* __restrict__ W,
                       const float* __restrict__ attn_l, const float* __restrict__ attn_r,
                       const float* __restrict__ W1, const float* __restrict__ b1,
                       const float* __restrict__ W2, const float* __restrict__ b2) {
    const int t = threadIdx.x;
    if (blockIdx.x == 0) {
        if (t < NHF) {
            float v = 0.f;
            #pragma unroll
            for (int j = 0; j < OUT_F; ++j) v += W1[t * OUT_F + j] * W2[j];
            g_vfold[t] = v;
        }
        if (t == 0) {
            float c = b2[0];
            for (int j = 0; j < OUT_F; ++j) c += b1[j] * W2[j];
            g_cfold = c;
        }
        // W^T (fp16): rows 0-63 = W[k][n] transposed
        for (int i = t; i < IN_F * NHF; i += 256) {
            int k = i >> 6, n = i & 63;
            g_wt_h[n * IN_F + k] = __float2half(W[i]);
        }
        // rows 64-67 = W@attn_l (h0,h1), W@attn_r (h0,h1); rows 68-71 = 0
        for (int i = t; i < IN_F * 8; i += 256) {
            int k = i & 127, nx = i >> 7;  // nx 0..7
            float v = 0.f;
            if (nx < 4) {
                const float* av = (nx & 2) ? attn_r : attn_l;
                int h = nx & 1;
                for (int f = 0; f < 32; ++f)
                    v += W[k * 64 + h * 32 + f] * av[h * 32 + f];
            }
            g_wt_h[(64 + nx) * IN_F + k] = __float2half(v);
        }
    }
    int i = blockIdx.x * blockDim.x + t;
    if (i * 4 >= N_EDGES) return;
    int4 d = *(const int4*)&dst[i * 4];
    atomicAdd(&g_deg[d.x], 1);
    atomicAdd(&g_deg[d.y], 1);
    atomicAdd(&g_deg[d.z], 1);
    atomicAdd(&g_deg[d.w], 1);
}

// ---- scan phase 1+2 fused: per-block sums; last block scans the 98 sums ----
__global__ void k_scan1() {
    __shared__ int s[SCAN_BLK];
    __shared__ int is_last;
    int i = blockIdx.x * SCAN_BLK + threadIdx.x;
    s[threadIdx.x] = (i < N_NODES) ? g_deg[i] : 0;
    __syncthreads();
    #pragma unroll
    for (int off = SCAN_BLK / 2; off > 0; off >>= 1) {
        if (threadIdx.x < off) s[threadIdx.x] += s[threadIdx.x + off];
        __syncthreads();
    }
    if (threadIdx.x == 0) {
        g_blksum[blockIdx.x] = s[0];
        __threadfence();
        int t = atomicAdd(&g_ticket, 1);
        is_last = (t == gridDim.x - 1);
    }
    __syncthreads();
    if (!is_last) return;
    __shared__ int s2[128];
    int t = threadIdx.x;
    if (t < 128) {
        int v = (t < N_SCAN_BLKS) ? g_blksum[t] : 0;
        s2[t] = v;
        __syncthreads();
        #pragma unroll
        for (int off = 1; off < 128; off <<= 1) {
            int u = (t >= off) ? s2[t - off] : 0;
            __syncthreads();
            s2[t] += u;
            __syncthreads();
        }
        if (t < N_SCAN_BLKS) g_blksum[t] = s2[t] - v;  // exclusive prefix
        if (t == 127) g_off[N_NODES] = s2[127];
        if (t == 0) g_ticket = 0;                      // restore invariant
    } else {
        __syncthreads();
        #pragma unroll
        for (int off = 1; off < 128; off <<= 1) { __syncthreads(); __syncthreads(); }
    }
}

// ---- scan phase 3: in-block exclusive scan + block offset; re-zero g_deg ----
__global__ void k_scan3() {
    __shared__ int s[SCAN_BLK];
    int i = blockIdx.x * SCAN_BLK + threadIdx.x;
    int v = (i < N_NODES) ? g_deg[i] : 0;
    s[threadIdx.x] = v;
    __syncthreads();
    #pragma unroll
    for (int off = 1; off < SCAN_BLK; off <<= 1) {
        int u = (threadIdx.x >= off) ? s[threadIdx.x - off] : 0;
        __syncthreads();
        s[threadIdx.x] += u;
        __syncthreads();
    }
    if (i < N_NODES) {
        int excl = g_blksum[blockIdx.x] + s[threadIdx.x] - v;
        g_off[i] = excl;
        g_cur[i] = excl;
        g_deg[i] = 0;
    }
}

// ---- standalone scatter (zero smem -> full occupancy for L2 atomics) ----
__global__ void k_scatter(const int* __restrict__ src, const int* __restrict__ dst) {
    int i = blockIdx.x * blockDim.x + threadIdx.x;
    if (i * 4 >= N_EDGES) return;
    int4 s = *(const int4*)&src[i * 4];
    int4 d = *(const int4*)&dst[i * 4];
    g_srcs[atomicAdd(&g_cur[d.x], 1)] = s.x;
    g_srcs[atomicAdd(&g_cur[d.y], 1)] = s.y;
    g_srcs[atomicAdd(&g_cur[d.z], 1)] = s.z;
    g_srcs[atomicAdd(&g_cur[d.w], 1)] = s.w;
}

// ---- tensor-core GEMM: [64 rows] x [128 k] x [72 n] per block ----
// n cols 0-63 = feat (stored fp16); cols 64-67 = el_h0, el_h1, er_h0, er_h1
// (W@attn folds), written at fp32 accumulator precision. mma.m16n8k16.
__device__ __forceinline__ void mma16816(float* c, uint32_t a0, uint32_t a1,
                                         uint32_t a2, uint32_t a3,
                                         uint32_t b0, uint32_t b1) {
    asm volatile(
        "mma.sync.aligned.m16n8k16.row.col.f32.f16.f16.f32 "
        "{%0,%1,%2,%3}, {%4,%5,%6,%7}, {%8,%9}, {%0,%1,%2,%3};"
        : "+f"(c[0]), "+f"(c[1]), "+f"(c[2]), "+f"(c[3])
        : "r"(a0), "r"(a1), "r"(a2), "r"(a3), "r"(b0), "r"(b1));
}

__global__ void k_gemm_mma(const float* __restrict__ x) {
    __shared__ __half Xs[64][136];   // [m][k] fp16, padded rows (272B)
    __shared__ __half Wts[72][136];  // [n][k] fp16, padded rows
    const int t = threadIdx.x;       // 128 threads
    const int block_row = blockIdx.x * 64;

    // load W^T tile (9216 halves, 16B chunks)
    for (int i = t; i < 72 * 16; i += 128) {
        int row = i >> 4, seg = i & 15;
        *(uint4*)&Wts[row][seg * 8] = *(const uint4*)&g_wt_h[row * IN_F + seg * 8];
    }
    // load + convert X tile (64 x 128 fp32 -> fp16)
    for (int i = t; i < 64 * 32; i += 128) {
        int row = i >> 5, c4 = i & 31;
        int gr = block_row + row;
        float4 v = make_float4(0.f, 0.f, 0.f, 0.f);
        if (gr < N_NODES) v = *(const float4*)&x[gr * IN_F + c4 * 4];
        *(__half2*)&Xs[row][c4 * 4] = __floats2half2_rn(v.x, v.y);
        *(__half2*)&Xs[row][c4 * 4 + 2] = __floats2half2_rn(v.z, v.w);
    }
    __syncthreads();

    const int w = t >> 5, lane = t & 31;
    const int q = lane >> 2, qq = lane & 3;
    const int r0 = w * 16 + q;        // local rows r0, r0+8

    float c[9][4];
    #pragma unroll
    for (int nt = 0; nt < 9; ++nt)
        #pragma unroll
        for (int j = 0; j < 4; ++j) c[nt][j] = 0.f;

    #pragma unroll
    for (int kt = 0; kt < 8; ++kt) {
        const int k0 = kt * 16 + qq * 2;
        uint32_t a0 = *(const uint32_t*)&Xs[r0][k0];
        uint32_t a1 = *(const uint32_t*)&Xs[r0 + 8][k0];
        uint32_t a2 = *(const uint32_t*)&Xs[r0][k0 + 8];
        uint32_t a3 = *(const uint32_t*)&Xs[r0 + 8][k0 + 8];
        #pragma unroll
        for (int nt = 0; nt < 9; ++nt) {
            uint32_t b0 = *(const uint32_t*)&Wts[nt * 8 + q][k0];
            uint32_t b1 = *(const uint32_t*)&Wts[nt * 8 + q][k0 + 8];
            mma16816(c[nt], a0, a1, a2, a3, b0, b1);
        }
    }

    // epilogue
    const int gr0 = block_row + r0;
    const int gr1 = gr0 + 8;
    #pragma unroll
    for (int nt = 0; nt < 8; ++nt) {
        int col = nt * 8 + qq * 2;
        if (gr0 < N_NODES)
            *(__half2*)&g_feat_h[gr0 * NHF + col] = __floats2half2_rn(c[nt][0], c[nt][1]);
        if (gr1 < N_NODES)
            *(__half2*)&g_feat_h[gr1 * NHF + col] = __floats2half2_rn(c[nt][2], c[nt][3]);
    }
    if (qq == 0) {          // cols 64,65 = el head0, head1
        if (gr0 < N_NODES) { g_el[gr0 * 2] = c[8][0]; g_el[gr0 * 2 + 1] = c[8][1]; }
        if (gr1 < N_NODES) { g_el[gr1 * 2] = c[8][2]; g_el[gr1 * 2 + 1] = c[8][3]; }
    } else if (qq == 1) {   // cols 66,67 = er head0, head1
        if (gr0 < N_NODES) { g_er[gr0 * 2] = c[8][0]; g_er[gr0 * 2 + 1] = c[8][1]; }
        if (gr1 < N_NODES) { g_er[gr1 * 2] = c[8][2]; g_er[gr1 * 2 + 1] = c[8][3]; }
    }
}

// ---- fused per-dst-node: softmax + aggregation + epilogue (warp per node) ----
__global__ void k_agg(const float* __restrict__ bias_gat) {
    int warp = (blockIdx.x * blockDim.x + threadIdx.x) >> 5;
    int lane = threadIdx.x & 31;
    if (warp >= N_NODES) return;
    const int n = warp;
    const int beg = g_off[n];
    const int end = g_off[n + 1];

    const float2 erd = *(const float2*)&g_er[n * 2];
    float2 acc = make_float2(0.f, 0.f);
    float den0 = 0.f, den1 = 0.f;

    for (int base = beg; base < end; base += 32) {
        const int cnt = min(32, end - base);
        int s = 0;
        float ex0 = 0.f, ex1 = 0.f;
        if (lane < cnt) {
            s = g_srcs[base + lane];
            float2 els = *(const float2*)&g_el[s * 2];
            float v0 = els.x + erd.x;
            float v1 = els.y + erd.y;
            v0 = v0 > 0.f ? v0 : 0.2f * v0;
            v1 = v1 > 0.f ? v1 : 0.2f * v1;
            ex0 = __expf(v0);
            ex1 = __expf(v1);
        }
        for (int j = 0; j < cnt; ++j) {
            int sj = __shfl_sync(0xFFFFFFFFu, s, j);
            float e0 = __shfl_sync(0xFFFFFFFFu, ex0, j);
            float e1 = __shfl_sync(0xFFFFFFFFu, ex1, j);
            __half2 fh = *(const __half2*)&g_feat_h[sj * NHF + 2 * lane];
            float2 f = __half22float2(fh);
            float w = (lane < 16) ? e0 : e1;
            acc.x = fmaf(w, f.x, acc.x);
            acc.y = fmaf(w, f.y, acc.y);
            den0 += e0;
            den1 += e1;
        }
    }

    float inv0 = (den0 > 0.f) ? 1.f / den0 : 0.f;
    float inv1 = (den1 > 0.f) ? 1.f / den1 : 0.f;
    float myinv = (lane < 16) ? inv0 : inv1;
    float rx = acc.x * myinv;
    float ry = acc.y * myinv;
    float ox = __shfl_xor_sync(0xFFFFFFFFu, rx, 16);
    float oy = __shfl_xor_sync(0xFFFFFFFFu, ry, 16);
    int c0 = 2 * (lane & 15);
    float2 bh0 = *(const float2*)&bias_gat[c0];
    float2 bh1 = *(const float2*)&bias_gat[32 + c0];
    float h0 = fmaxf(0.5f * (rx + ox + bh0.x + bh1.x), 0.f);
    float h1 = fmaxf(0.5f * (ry + oy + bh0.y + bh1.y), 0.f);
    float2 va = *(const float2*)&g_vfold[c0];
    float2 vb = *(const float2*)&g_vfold[32 + c0];
    float av = h0 * va.x + h1 * va.y;
    float bv = h0 * vb.x + h1 * vb.y;
    #pragma unroll
    for (int o = 1; o < 16; o <<= 1) {
        av += __shfl_xor_sync(0xFFFFFFFFu, av, o);
        bv += __shfl_xor_sync(0xFFFFFFFFu, bv, o);
    }
    if (lane == 0) { g_a[n] = av; g_b[n] = bv; }
}

// ---- per-edge final score (4 edges per thread) ----
__global__ void k_edge_score(const int* __restrict__ src, const int* __restrict__ dst,
                             float* __restrict__ out) {
    int i = blockIdx.x * blockDim.x + threadIdx.x;
    if (i * 4 >= N_EDGES) return;
    int4 s = *(const int4*)&src[i * 4];
    int4 d = *(const int4*)&dst[i * 4];
    float c = g_cfold;
    float4 r;
    r.x = g_a[s.x] + g_b[d.x] + c;
    r.y = g_a[s.y] + g_b[d.y] + c;
    r.z = g_a[s.z] + g_b[d.z] + c;
    r.w = g_a[s.w] + g_b[d.w] + c;
    *(float4*)&out[i * 4] = r;
}

extern "C" void kernel_launch(void* const* d_in, const int* in_sizes, int n_in,
                              void* d_out, int out_size) {
    const float* x       = (const float*)d_in[0];
    const float* W       = (const float*)d_in[1];
    const float* attn_l  = (const float*)d_in[2];
    const float* attn_r  = (const float*)d_in[3];
    const float* bias_gat= (const float*)d_in[4];
    const float* W1      = (const float*)d_in[5];
    const float* b1      = (const float*)d_in[6];
    const float* W2      = (const float*)d_in[7];
    const float* b2      = (const float*)d_in[8];
    const int*   src     = (const int*)d_in[9];
    const int*   dst     = (const int*)d_in[10];
    float* out = (float*)d_out;

    k_hist<<<(N_EDGES / 4 + 255) / 256, 256>>>(dst, W, attn_l, attn_r, W1, b1, W2, b2);
    k_scan1<<<N_SCAN_BLKS, SCAN_BLK>>>();
    k_scan3<<<N_SCAN_BLKS, SCAN_BLK>>>();
    k_gemm_mma<<<GEMM_BLKS, 128>>>(x);
    k_scatter<<<(N_EDGES / 4 + 255) / 256, 256>>>(src, dst);
    k_agg<<<(N_NODES * 32 + 255) / 256, 256>>>(bias_gat);
    k_edge_score<<<(N_EDGES / 4 + 255) / 256, 256>>>(src, dst, out);
}

// round 15
// speedup vs baseline: 1.1708x; 1.0345x over previous
#include <cuda_runtime.h>
#include <cuda_bf16.h>
#include <cuda_fp16.h>
#include <cstdint>

#define N_NODES 100000
#define N_EDGES 1600000
#define IN_F 128
#define OUT_F 32
#define HEADS 2
#define NHF 64  // HEADS*OUT_F
#define SCAN_BLK 1024
#define N_SCAN_BLKS ((N_NODES + SCAN_BLK - 1) / SCAN_BLK)  // 98
#define GEMM_BLKS ((N_NODES + 127) / 128)                   // 782

// ---- scratch (device globals; zero-initialized at module load) ----
__device__ __half g_feat_h[N_NODES * NHF];  // fp16 feat for the agg gathers
__device__ __half g_wt_h[72 * IN_F];        // B^T fp16: [n][k]; rows 64-67 = wl/wr folds
__device__ float g_el[N_NODES * HEADS];
__device__ float g_er[N_NODES * HEADS];
__device__ float g_a[N_NODES];
__device__ float g_b[N_NODES];
__device__ float g_vfold[NHF];
__device__ float g_cfold;
// CSR-by-dst scratch. INVARIANT: g_deg all-zero at entry (zero-init at load;
// k_scan3 re-zeroes each run). g_ticket reset by k_scan1's last block.
__device__ int g_deg[N_NODES];
__device__ int g_cur[N_NODES];
__device__ int g_off[N_NODES + 1];
__device__ int g_srcs[N_EDGES];
__device__ int g_blksum[N_SCAN_BLKS];
__device__ int g_ticket;

// ---- hist (4 edges/thread) + block 0: MLP fold, W transpose+fold to fp16 ----
__global__ void k_hist(const int* __restrict__ dst,
                       const float* __restrict__ W,
                       const float* __restrict__ attn_l, const float* __restrict__ attn_r,
                       const float* __restrict__ W1, const float* __restrict__ b1,
                       const float* __restrict__ W2, const float* __restrict__ b2) {
    const int t = threadIdx.x;
    if (blockIdx.x == 0) {
        if (t < NHF) {
            float v = 0.f;
            #pragma unroll
            for (int j = 0; j < OUT_F; ++j) v += W1[t * OUT_F + j] * W2[j];
            g_vfold[t] = v;
        }
        if (t == 0) {
            float c = b2[0];
            for (int j = 0; j < OUT_F; ++j) c += b1[j] * W2[j];
            g_cfold = c;
        }
        // W^T (fp16): rows 0-63 = W[k][n] transposed
        for (int i = t; i < IN_F * NHF; i += 256) {
            int k = i >> 6, n = i & 63;
            g_wt_h[n * IN_F + k] = __float2half(W[i]);
        }
        // rows 64-67 = W@attn_l (h0,h1), W@attn_r (h0,h1); rows 68-71 = 0
        for (int i = t; i < IN_F * 8; i += 256) {
            int k = i & 127, nx = i >> 7;  // nx 0..7
            float v = 0.f;
            if (nx < 4) {
                const float* av = (nx & 2) ? attn_r : attn_l;
                int h = nx & 1;
                for (int f = 0; f < 32; ++f)
                    v += W[k * 64 + h * 32 + f] * av[h * 32 + f];
            }
            g_wt_h[(64 + nx) * IN_F + k] = __float2half(v);
        }
    }
    int i = blockIdx.x * blockDim.x + t;
    if (i * 4 >= N_EDGES) return;
    int4 d = *(const int4*)&dst[i * 4];
    atomicAdd(&g_deg[d.x], 1);
    atomicAdd(&g_deg[d.y], 1);
    atomicAdd(&g_deg[d.z], 1);
    atomicAdd(&g_deg[d.w], 1);
}

// ---- scan phase 1+2 fused: per-block sums; last block scans the 98 sums ----
__global__ void k_scan1() {
    __shared__ int s[SCAN_BLK];
    __shared__ int is_last;
    int i = blockIdx.x * SCAN_BLK + threadIdx.x;
    s[threadIdx.x] = (i < N_NODES) ? g_deg[i] : 0;
    __syncthreads();
    #pragma unroll
    for (int off = SCAN_BLK / 2; off > 0; off >>= 1) {
        if (threadIdx.x < off) s[threadIdx.x] += s[threadIdx.x + off];
        __syncthreads();
    }
    if (threadIdx.x == 0) {
        g_blksum[blockIdx.x] = s[0];
        __threadfence();
        int t = atomicAdd(&g_ticket, 1);
        is_last = (t == gridDim.x - 1);
    }
    __syncthreads();
    if (!is_last) return;
    __shared__ int s2[128];
    int t = threadIdx.x;
    if (t < 128) {
        int v = (t < N_SCAN_BLKS) ? g_blksum[t] : 0;
        s2[t] = v;
        __syncthreads();
        #pragma unroll
        for (int off = 1; off < 128; off <<= 1) {
            int u = (t >= off) ? s2[t - off] : 0;
            __syncthreads();
            s2[t] += u;
            __syncthreads();
        }
        if (t < N_SCAN_BLKS) g_blksum[t] = s2[t] - v;  // exclusive prefix
        if (t == 127) g_off[N_NODES] = s2[127];
        if (t == 0) g_ticket = 0;                      // restore invariant
    } else {
        __syncthreads();
        #pragma unroll
        for (int off = 1; off < 128; off <<= 1) { __syncthreads(); __syncthreads(); }
    }
}

// ---- scan phase 3: in-block exclusive scan + block offset; re-zero g_deg ----
__global__ void k_scan3() {
    __shared__ int s[SCAN_BLK];
    int i = blockIdx.x * SCAN_BLK + threadIdx.x;
    int v = (i < N_NODES) ? g_deg[i] : 0;
    s[threadIdx.x] = v;
    __syncthreads();
    #pragma unroll
    for (int off = 1; off < SCAN_BLK; off <<= 1) {
        int u = (threadIdx.x >= off) ? s[threadIdx.x - off] : 0;
        __syncthreads();
        s[threadIdx.x] += u;
        __syncthreads();
    }
    if (i < N_NODES) {
        int excl = g_blksum[blockIdx.x] + s[threadIdx.x] - v;
        g_off[i] = excl;
        g_cur[i] = excl;
        g_deg[i] = 0;
    }
}

// ---- standalone scatter (zero smem -> full occupancy for L2 atomics) ----
__global__ void k_scatter(const int* __restrict__ src, const int* __restrict__ dst) {
    int i = blockIdx.x * blockDim.x + threadIdx.x;
    if (i * 4 >= N_EDGES) return;
    int4 s = *(const int4*)&src[i * 4];
    int4 d = *(const int4*)&dst[i * 4];
    g_srcs[atomicAdd(&g_cur[d.x], 1)] = s.x;
    g_srcs[atomicAdd(&g_cur[d.y], 1)] = s.y;
    g_srcs[atomicAdd(&g_cur[d.z], 1)] = s.z;
    g_srcs[atomicAdd(&g_cur[d.w], 1)] = s.w;
}

// ---- tensor-core GEMM: [128 rows] x [128 k] x [72 n] per block, 256 thr ----
__device__ __forceinline__ void mma16816(float* c, uint32_t a0, uint32_t a1,
                                         uint32_t a2, uint32_t a3,
                                         uint32_t b0, uint32_t b1) {
    asm volatile(
        "mma.sync.aligned.m16n8k16.row.col.f32.f16.f16.f32 "
        "{%0,%1,%2,%3}, {%4,%5,%6,%7}, {%8,%9}, {%0,%1,%2,%3};"
        : "+f"(c[0]), "+f"(c[1]), "+f"(c[2]), "+f"(c[3])
        : "r"(a0), "r"(a1), "r"(a2), "r"(a3), "r"(b0), "r"(b1));
}

__global__ void __launch_bounds__(256, 4) k_gemm_mma(const float* __restrict__ x) {
    __shared__ __half Xs[128][136];  // [m][k] fp16, padded rows (272B)
    __shared__ __half Wts[72][136];  // [n][k] fp16, padded rows
    const int t = threadIdx.x;       // 256 threads, 8 warps
    const int block_row = blockIdx.x * 128;

    // load W^T tile (72 x 16 chunks of 8 halves)
    for (int i = t; i < 72 * 16; i += 256) {
        int row = i >> 4, seg = i & 15;
        *(uint4*)&Wts[row][seg * 8] = *(const uint4*)&g_wt_h[row * IN_F + seg * 8];
    }
    // load + convert X tile (128 x 128 fp32 -> fp16)
    for (int i = t; i < 128 * 32; i += 256) {
        int row = i >> 5, c4 = i & 31;
        int gr = block_row + row;
        float4 v = make_float4(0.f, 0.f, 0.f, 0.f);
        if (gr < N_NODES) v = *(const float4*)&x[gr * IN_F + c4 * 4];
        *(__half2*)&Xs[row][c4 * 4] = __floats2half2_rn(v.x, v.y);
        *(__half2*)&Xs[row][c4 * 4 + 2] = __floats2half2_rn(v.z, v.w);
    }
    __syncthreads();

    const int w = t >> 5, lane = t & 31;
    const int q = lane >> 2, qq = lane & 3;
    const int r0 = w * 16 + q;        // local rows r0, r0+8

    float c[9][4];
    #pragma unroll
    for (int nt = 0; nt < 9; ++nt)
        #pragma unroll
        for (int j = 0; j < 4; ++j) c[nt][j] = 0.f;

    #pragma unroll
    for (int kt = 0; kt < 8; ++kt) {
        const int k0 = kt * 16 + qq * 2;
        uint32_t a0 = *(const uint32_t*)&Xs[r0][k0];
        uint32_t a1 = *(const uint32_t*)&Xs[r0 + 8][k0];
        uint32_t a2 = *(const uint32_t*)&Xs[r0][k0 + 8];
        uint32_t a3 = *(const uint32_t*)&Xs[r0 + 8][k0 + 8];
        #pragma unroll
        for (int nt = 0; nt < 9; ++nt) {
            uint32_t b0 = *(const uint32_t*)&Wts[nt * 8 + q][k0];
            uint32_t b1 = *(const uint32_t*)&Wts[nt * 8 + q][k0 + 8];
            mma16816(c[nt], a0, a1, a2, a3, b0, b1);
        }
    }

    // epilogue
    const int gr0 = block_row + r0;
    const int gr1 = gr0 + 8;
    #pragma unroll
    for (int nt = 0; nt < 8; ++nt) {
        int col = nt * 8 + qq * 2;
        if (gr0 < N_NODES)
            *(__half2*)&g_feat_h[gr0 * NHF + col] = __floats2half2_rn(c[nt][0], c[nt][1]);
        if (gr1 < N_NODES)
            *(__half2*)&g_feat_h[gr1 * NHF + col] = __floats2half2_rn(c[nt][2], c[nt][3]);
    }
    if (qq == 0) {          // cols 64,65 = el head0, head1
        if (gr0 < N_NODES) { g_el[gr0 * 2] = c[8][0]; g_el[gr0 * 2 + 1] = c[8][1]; }
        if (gr1 < N_NODES) { g_el[gr1 * 2] = c[8][2]; g_el[gr1 * 2 + 1] = c[8][3]; }
    } else if (qq == 1) {   // cols 66,67 = er head0, head1
        if (gr0 < N_NODES) { g_er[gr0 * 2] = c[8][0]; g_er[gr0 * 2 + 1] = c[8][1]; }
        if (gr1 < N_NODES) { g_er[gr1 * 2] = c[8][2]; g_er[gr1 * 2 + 1] = c[8][3]; }
    }
}

// ---- fused per-dst-node: softmax + aggregation + epilogue (warp per node) ----
// 2 edges per inner iteration: lanes 0-15 = edge 2j, lanes 16-31 = edge 2j+1.
// Each lane gathers 4 halves (cols 4L..4L+3 of the 64-col combined row).
__global__ void k_agg(const float* __restrict__ bias_gat) {
    int warp = (blockIdx.x * blockDim.x + threadIdx.x) >> 5;
    int lane = threadIdx.x & 31;
    if (warp >= N_NODES) return;
    const int n = warp;
    const int beg = g_off[n];
    const int end = g_off[n + 1];

    const float2 erd = *(const float2*)&g_er[n * 2];
    const int half = lane >> 4;       // which edge of the pair
    const int li = lane & 15;
    const int coff = 4 * li;          // my 4 columns
    const bool is_h0 = (li < 8);      // cols 0-31 = head0

    float4 acc = make_float4(0.f, 0.f, 0.f, 0.f);
    float den0 = 0.f, den1 = 0.f;

    for (int base = beg; base < end; base += 32) {
        const int cnt = min(32, end - base);
        int s = 0;
        float ex0 = 0.f, ex1 = 0.f;
        if (lane < cnt) {
            s = g_srcs[base + lane];
            float2 els = *(const float2*)&g_el[s * 2];
            float v0 = els.x + erd.x;
            float v1 = els.y + erd.y;
            v0 = v0 > 0.f ? v0 : 0.2f * v0;
            v1 = v1 > 0.f ? v1 : 0.2f * v1;
            ex0 = __expf(v0);
            ex1 = __expf(v1);
            den0 += ex0;             // denom accumulated once per edge here
            den1 += ex1;
        }
        const int pairs = (cnt + 1) >> 1;
        for (int j = 0; j < pairs; ++j) {
            int idx = 2 * j + half;  // >=cnt lanes give s=0, ex=0 (safe)
            int sj = __shfl_sync(0xFFFFFFFFu, s, idx);
            float e0 = __shfl_sync(0xFFFFFFFFu, ex0, idx);
            float e1 = __shfl_sync(0xFFFFFFFFu, ex1, idx);
            float wgt = is_h0 ? e0 : e1;
            uint2 fh = *(const uint2*)&g_feat_h[sj * NHF + coff];
            float2 f01 = __half22float2(*(__half2*)&fh.x);
            float2 f23 = __half22float2(*(__half2*)&fh.y);
            acc.x = fmaf(wgt, f01.x, acc.x);
            acc.y = fmaf(wgt, f01.y, acc.y);
            acc.z = fmaf(wgt, f23.x, acc.z);
            acc.w = fmaf(wgt, f23.y, acc.w);
        }
    }

    // combine the two 16-lane halves (same columns, disjoint edge subsets)
    acc.x += __shfl_xor_sync(0xFFFFFFFFu, acc.x, 16);
    acc.y += __shfl_xor_sync(0xFFFFFFFFu, acc.y, 16);
    acc.z += __shfl_xor_sync(0xFFFFFFFFu, acc.z, 16);
    acc.w += __shfl_xor_sync(0xFFFFFFFFu, acc.w, 16);
    // full-warp denom reduce
    #pragma unroll
    for (int o = 1; o < 32; o <<= 1) {
        den0 += __shfl_xor_sync(0xFFFFFFFFu, den0, o);
        den1 += __shfl_xor_sync(0xFFFFFFFFu, den1, o);
    }
    float inv0 = (den0 > 0.f) ? 1.f / den0 : 0.f;
    float inv1 = (den1 > 0.f) ? 1.f / den1 : 0.f;
    float myinv = is_h0 ? inv0 : inv1;
    float r0 = acc.x * myinv, r1 = acc.y * myinv;
    float r2 = acc.z * myinv, r3 = acc.w * myinv;
    // head swap: lane li (0-7) holds head0 f=4li..4li+3; lane li+8 head1 same f
    float o0 = __shfl_xor_sync(0xFFFFFFFFu, r0, 8);
    float o1 = __shfl_xor_sync(0xFFFFFFFFu, r1, 8);
    float o2 = __shfl_xor_sync(0xFFFFFFFFu, r2, 8);
    float o3 = __shfl_xor_sync(0xFFFFFFFFu, r3, 8);
    float4 b0 = *(const float4*)&bias_gat[coff & 31];
    float4 b1 = *(const float4*)&bias_gat[32 + (coff & 31)];
    float h0 = fmaxf(0.5f * (r0 + o0 + b0.x + b1.x), 0.f);
    float h1 = fmaxf(0.5f * (r1 + o1 + b0.y + b1.y), 0.f);
    float h2 = fmaxf(0.5f * (r2 + o2 + b0.z + b1.z), 0.f);
    float h3 = fmaxf(0.5f * (r3 + o3 + b0.w + b1.w), 0.f);
    float4 va = *(const float4*)&g_vfold[coff & 31];
    float4 vb = *(const float4*)&g_vfold[32 + (coff & 31)];
    float av = h0 * va.x + h1 * va.y + h2 * va.z + h3 * va.w;
    float bv = h0 * vb.x + h1 * vb.y + h2 * vb.z + h3 * vb.w;
    // reduce within the 8-lane group (lanes 0-7 hold the real values)
    #pragma unroll
    for (int o = 1; o < 8; o <<= 1) {
        av += __shfl_xor_sync(0xFFFFFFFFu, av, o);
        bv += __shfl_xor_sync(0xFFFFFFFFu, bv, o);
    }
    if (lane == 0) { g_a[n] = av; g_b[n] = bv; }
}

// ---- per-edge final score (4 edges per thread) ----
__global__ void k_edge_score(const int* __restrict__ src, const int* __restrict__ dst,
                             float* __restrict__ out) {
    int i = blockIdx.x * blockDim.x + threadIdx.x;
    if (i * 4 >= N_EDGES) return;
    int4 s = *(const int4*)&src[i * 4];
    int4 d = *(const int4*)&dst[i * 4];
    float c = g_cfold;
    float4 r;
    r.x = g_a[s.x] + g_b[d.x] + c;
    r.y = g_a[s.y] + g_b[d.y] + c;
    r.z = g_a[s.z] + g_b[d.z] + c;
    r.w = g_a[s.w] + g_b[d.w] + c;
    *(float4*)&out[i * 4] = r;
}

extern "C" void kernel_launch(void* const* d_in, const int* in_sizes, int n_in,
                              void* d_out, int out_size) {
    const float* x       = (const float*)d_in[0];
    const float* W       = (const float*)d_in[1];
    const float* attn_l  = (const float*)d_in[2];
    const float* attn_r  = (const float*)d_in[3];
    const float* bias_gat= (const float*)d_in[4];
    const float* W1      = (const float*)d_in[5];
    const float* b1      = (const float*)d_in[6];
    const float* W2      = (const float*)d_in[7];
    const float* b2      = (const float*)d_in[8];
    const int*   src     = (const int*)d_in[9];
    const int*   dst     = (const int*)d_in[10];
    float* out = (float*)d_out;

    k_hist<<<(N_EDGES / 4 + 255) / 256, 256>>>(dst, W, attn_l, attn_r, W1, b1, W2, b2);
    k_scan1<<<N_SCAN_BLKS, SCAN_BLK>>>();
    k_scan3<<<N_SCAN_BLKS, SCAN_BLK>>>();
    k_gemm_mma<<<GEMM_BLKS, 256>>>(x);
    k_scatter<<<(N_EDGES / 4 + 255) / 256, 256>>>(src, dst);
    k_agg<<<(N_NODES * 32 + 255) / 256, 256>>>(bias_gat);
    k_edge_score<<<(N_EDGES / 4 + 255) / 256, 256>>>(src, dst, out);
}

// round 16
// speedup vs baseline: 1.3145x; 1.1227x over previous
#include <cuda_runtime.h>
#include <cuda_bf16.h>
#include <cuda_fp16.h>
#include <cstdint>

#define N_NODES 100000
#define N_EDGES 1600000
#define IN_F 128
#define OUT_F 32
#define HEADS 2
#define NHF 64  // HEADS*OUT_F
#define SCAN_BLK 1024
#define N_SCAN_BLKS ((N_NODES + SCAN_BLK - 1) / SCAN_BLK)  // 98
#define GEMM_TILES ((N_NODES + 127) / 128)                  // 782
#define GEMM_GRID 592                                       // 148 SMs x 4 blocks

// ---- scratch (device globals; zero-initialized at module load) ----
__device__ __half g_feat_h[N_NODES * NHF];  // fp16 feat for the agg gathers
__device__ __half g_wt_h[72 * IN_F];        // B^T fp16: [n][k]; rows 64-67 = wl/wr folds
__device__ float g_el[N_NODES * HEADS];
__device__ float g_er[N_NODES * HEADS];
__device__ float g_a[N_NODES];
__device__ float g_b[N_NODES];
__device__ float g_vfold[NHF];
__device__ float g_cfold;
// CSR-by-dst scratch. INVARIANT: g_deg all-zero at entry (zero-init at load;
// k_scan3 re-zeroes each run). g_ticket reset by k_scan1's last block.
__device__ int g_deg[N_NODES];
__device__ int g_cur[N_NODES];
__device__ int g_off[N_NODES + 1];
__device__ int g_srcs[N_EDGES];
__device__ int g_blksum[N_SCAN_BLKS];
__device__ int g_ticket;

// ---- hist (4 edges/thread) + block 0: MLP fold, W transpose+fold to fp16 ----
__global__ void k_hist(const int* __restrict__ dst,
                       const float* __restrict__ W,
                       const float* __restrict__ attn_l, const float* __restrict__ attn_r,
                       const float* __restrict__ W1, const float* __restrict__ b1,
                       const float* __restrict__ W2, const float* __restrict__ b2) {
    const int t = threadIdx.x;
    if (blockIdx.x == 0) {
        if (t < NHF) {
            float v = 0.f;
            #pragma unroll
            for (int j = 0; j < OUT_F; ++j) v += W1[t * OUT_F + j] * W2[j];
            g_vfold[t] = v;
        }
        if (t == 0) {
            float c = b2[0];
            for (int j = 0; j < OUT_F; ++j) c += b1[j] * W2[j];
            g_cfold = c;
        }
        // W^T (fp16): rows 0-63 = W[k][n] transposed
        for (int i = t; i < IN_F * NHF; i += 256) {
            int k = i >> 6, n = i & 63;
            g_wt_h[n * IN_F + k] = __float2half(W[i]);
        }
        // rows 64-67 = W@attn_l (h0,h1), W@attn_r (h0,h1); rows 68-71 = 0
        for (int i = t; i < IN_F * 8; i += 256) {
            int k = i & 127, nx = i >> 7;  // nx 0..7
            float v = 0.f;
            if (nx < 4) {
                const float* av = (nx & 2) ? attn_r : attn_l;
                int h = nx & 1;
                for (int f = 0; f < 32; ++f)
                    v += W[k * 64 + h * 32 + f] * av[h * 32 + f];
            }
            g_wt_h[(64 + nx) * IN_F + k] = __float2half(v);
        }
    }
    int i = blockIdx.x * blockDim.x + t;
    if (i * 4 >= N_EDGES) return;
    int4 d = *(const int4*)&dst[i * 4];
    atomicAdd(&g_deg[d.x], 1);
    atomicAdd(&g_deg[d.y], 1);
    atomicAdd(&g_deg[d.z], 1);
    atomicAdd(&g_deg[d.w], 1);
}

// ---- scan phase 1+2 fused: per-block sums; last block scans the 98 sums ----
__global__ void k_scan1() {
    __shared__ int s[SCAN_BLK];
    __shared__ int is_last;
    int i = blockIdx.x * SCAN_BLK + threadIdx.x;
    s[threadIdx.x] = (i < N_NODES) ? g_deg[i] : 0;
    __syncthreads();
    #pragma unroll
    for (int off = SCAN_BLK / 2; off > 0; off >>= 1) {
        if (threadIdx.x < off) s[threadIdx.x] += s[threadIdx.x + off];
        __syncthreads();
    }
    if (threadIdx.x == 0) {
        g_blksum[blockIdx.x] = s[0];
        __threadfence();
        int t = atomicAdd(&g_ticket, 1);
        is_last = (t == gridDim.x - 1);
    }
    __syncthreads();
    if (!is_last) return;
    __shared__ int s2[128];
    int t = threadIdx.x;
    if (t < 128) {
        int v = (t < N_SCAN_BLKS) ? g_blksum[t] : 0;
        s2[t] = v;
        __syncthreads();
        #pragma unroll
        for (int off = 1; off < 128; off <<= 1) {
            int u = (t >= off) ? s2[t - off] : 0;
            __syncthreads();
            s2[t] += u;
            __syncthreads();
        }
        if (t < N_SCAN_BLKS) g_blksum[t] = s2[t] - v;  // exclusive prefix
        if (t == 127) g_off[N_NODES] = s2[127];
        if (t == 0) g_ticket = 0;                      // restore invariant
    } else {
        __syncthreads();
        #pragma unroll
        for (int off = 1; off < 128; off <<= 1) { __syncthreads(); __syncthreads(); }
    }
}

// ---- scan phase 3: in-block exclusive scan + block offset; re-zero g_deg ----
__global__ void k_scan3() {
    __shared__ int s[SCAN_BLK];
    int i = blockIdx.x * SCAN_BLK + threadIdx.x;
    int v = (i < N_NODES) ? g_deg[i] : 0;
    s[threadIdx.x] = v;
    __syncthreads();
    #pragma unroll
    for (int off = 1; off < SCAN_BLK; off <<= 1) {
        int u = (threadIdx.x >= off) ? s[threadIdx.x - off] : 0;
        __syncthreads();
        s[threadIdx.x] += u;
        __syncthreads();
    }
    if (i < N_NODES) {
        int excl = g_blksum[blockIdx.x] + s[threadIdx.x] - v;
        g_off[i] = excl;
        g_cur[i] = excl;
        g_deg[i] = 0;
    }
}

// ---- standalone scatter (zero smem -> full occupancy for L2 atomics) ----
__global__ void k_scatter(const int* __restrict__ src, const int* __restrict__ dst) {
    int i = blockIdx.x * blockDim.x + threadIdx.x;
    if (i * 4 >= N_EDGES) return;
    int4 s = *(const int4*)&src[i * 4];
    int4 d = *(const int4*)&dst[i * 4];
    g_srcs[atomicAdd(&g_cur[d.x], 1)] = s.x;
    g_srcs[atomicAdd(&g_cur[d.y], 1)] = s.y;
    g_srcs[atomicAdd(&g_cur[d.z], 1)] = s.z;
    g_srcs[atomicAdd(&g_cur[d.w], 1)] = s.w;
}

// ---- persistent tensor-core GEMM: one wave of 592 blocks strides tiles ----
__device__ __forceinline__ void mma16816(float* c, uint32_t a0, uint32_t a1,
                                         uint32_t a2, uint32_t a3,
                                         uint32_t b0, uint32_t b1) {
    asm volatile(
        "mma.sync.aligned.m16n8k16.row.col.f32.f16.f16.f32 "
        "{%0,%1,%2,%3}, {%4,%5,%6,%7}, {%8,%9}, {%0,%1,%2,%3};"
        : "+f"(c[0]), "+f"(c[1]), "+f"(c[2]), "+f"(c[3])
        : "r"(a0), "r"(a1), "r"(a2), "r"(a3), "r"(b0), "r"(b1));
}

__global__ void __launch_bounds__(256, 4) k_gemm_mma(const float* __restrict__ x) {
    __shared__ __half Xs[128][136];  // [m][k] fp16, padded rows (272B)
    __shared__ __half Wts[72][136];  // [n][k] fp16, padded rows
    const int t = threadIdx.x;       // 256 threads, 8 warps
    const int w = t >> 5, lane = t & 31;
    const int q = lane >> 2, qq = lane & 3;
    const int r0 = w * 16 + q;       // local rows r0, r0+8

    // W^T tile loaded once per (persistent) block
    for (int i = t; i < 72 * 16; i += 256) {
        int row = i >> 4, seg = i & 15;
        *(uint4*)&Wts[row][seg * 8] = *(const uint4*)&g_wt_h[row * IN_F + seg * 8];
    }

    for (int tile = blockIdx.x; tile < GEMM_TILES; tile += GEMM_GRID) {
        const int block_row = tile * 128;
        __syncthreads();   // previous iteration's MMA reads done; Wt ready (iter 0)

        if (block_row + 128 <= N_NODES) {
            // interior fast path: 16 unconditional batched LDG.128
            #pragma unroll
            for (int i = t; i < 128 * 32; i += 256) {
                int row = i >> 5, c4 = i & 31;
                float4 v = *(const float4*)&x[(block_row + row) * IN_F + c4 * 4];
                *(__half2*)&Xs[row][c4 * 4] = __floats2half2_rn(v.x, v.y);
                *(__half2*)&Xs[row][c4 * 4 + 2] = __floats2half2_rn(v.z, v.w);
            }
        } else {
            for (int i = t; i < 128 * 32; i += 256) {
                int row = i >> 5, c4 = i & 31;
                int gr = block_row + row;
                float4 v = make_float4(0.f, 0.f, 0.f, 0.f);
                if (gr < N_NODES) v = *(const float4*)&x[gr * IN_F + c4 * 4];
                *(__half2*)&Xs[row][c4 * 4] = __floats2half2_rn(v.x, v.y);
                *(__half2*)&Xs[row][c4 * 4 + 2] = __floats2half2_rn(v.z, v.w);
            }
        }
        __syncthreads();

        float c[9][4];
        #pragma unroll
        for (int nt = 0; nt < 9; ++nt)
            #pragma unroll
            for (int j = 0; j < 4; ++j) c[nt][j] = 0.f;

        #pragma unroll
        for (int kt = 0; kt < 8; ++kt) {
            const int k0 = kt * 16 + qq * 2;
            uint32_t a0 = *(const uint32_t*)&Xs[r0][k0];
            uint32_t a1 = *(const uint32_t*)&Xs[r0 + 8][k0];
            uint32_t a2 = *(const uint32_t*)&Xs[r0][k0 + 8];
            uint32_t a3 = *(const uint32_t*)&Xs[r0 + 8][k0 + 8];
            #pragma unroll
            for (int nt = 0; nt < 9; ++nt) {
                uint32_t b0 = *(const uint32_t*)&Wts[nt * 8 + q][k0];
                uint32_t b1 = *(const uint32_t*)&Wts[nt * 8 + q][k0 + 8];
                mma16816(c[nt], a0, a1, a2, a3, b0, b1);
            }
        }

        // epilogue
        const int gr0 = block_row + r0;
        const int gr1 = gr0 + 8;
        #pragma unroll
        for (int nt = 0; nt < 8; ++nt) {
            int col = nt * 8 + qq * 2;
            if (gr0 < N_NODES)
                *(__half2*)&g_feat_h[gr0 * NHF + col] = __floats2half2_rn(c[nt][0], c[nt][1]);
            if (gr1 < N_NODES)
                *(__half2*)&g_feat_h[gr1 * NHF + col] = __floats2half2_rn(c[nt][2], c[nt][3]);
        }
        if (qq == 0) {          // cols 64,65 = el head0, head1
            if (gr0 < N_NODES) { g_el[gr0 * 2] = c[8][0]; g_el[gr0 * 2 + 1] = c[8][1]; }
            if (gr1 < N_NODES) { g_el[gr1 * 2] = c[8][2]; g_el[gr1 * 2 + 1] = c[8][3]; }
        } else if (qq == 1) {   // cols 66,67 = er head0, head1
            if (gr0 < N_NODES) { g_er[gr0 * 2] = c[8][0]; g_er[gr0 * 2 + 1] = c[8][1]; }
            if (gr1 < N_NODES) { g_er[gr1 * 2] = c[8][2]; g_er[gr1 * 2 + 1] = c[8][3]; }
        }
    }
}

// ---- fused per-dst-node: softmax + aggregation + epilogue (warp per node) ----
// 2 edges per inner iteration, manually unrolled x2 (4 edges, 2 gathers in
// flight) for L2-latency MLP.
__global__ void k_agg(const float* __restrict__ bias_gat) {
    int warp = (blockIdx.x * blockDim.x + threadIdx.x) >> 5;
    int lane = threadIdx.x & 31;
    if (warp >= N_NODES) return;
    const int n = warp;
    const int beg = g_off[n];
    const int end = g_off[n + 1];

    const float2 erd = *(const float2*)&g_er[n * 2];
    const int half = lane >> 4;       // which edge of the pair
    const int li = lane & 15;
    const int coff = 4 * li;          // my 4 columns
    const bool is_h0 = (li < 8);      // cols 0-31 = head0

    float4 acc = make_float4(0.f, 0.f, 0.f, 0.f);
    float den0 = 0.f, den1 = 0.f;

    for (int base = beg; base < end; base += 32) {
        const int cnt = min(32, end - base);
        int s = 0;
        float ex0 = 0.f, ex1 = 0.f;
        if (lane < cnt) {
            s = g_srcs[base + lane];
            float2 els = *(const float2*)&g_el[s * 2];
            float v0 = els.x + erd.x;
            float v1 = els.y + erd.y;
            v0 = v0 > 0.f ? v0 : 0.2f * v0;
            v1 = v1 > 0.f ? v1 : 0.2f * v1;
            ex0 = __expf(v0);
            ex1 = __expf(v1);
            den0 += ex0;             // denom accumulated once per edge here
            den1 += ex1;
        }
        const int pairs = (cnt + 1) >> 1;
        int j = 0;
        for (; j + 2 <= pairs; j += 2) {
            int idxA = 2 * j + half;
            int idxB = 2 * j + 2 + half;
            int sA = __shfl_sync(0xFFFFFFFFu, s, idxA);
            int sB = __shfl_sync(0xFFFFFFFFu, s, idxB);
            float e0A = __shfl_sync(0xFFFFFFFFu, ex0, idxA);
            float e1A = __shfl_sync(0xFFFFFFFFu, ex1, idxA);
            float e0B = __shfl_sync(0xFFFFFFFFu, ex0, idxB);
            float e1B = __shfl_sync(0xFFFFFFFFu, ex1, idxB);
            uint2 fhA = *(const uint2*)&g_feat_h[sA * NHF + coff];
            uint2 fhB = *(const uint2*)&g_feat_h[sB * NHF + coff];
            float wA = is_h0 ? e0A : e1A;
            float wB = is_h0 ? e0B : e1B;
            float2 a01 = __half22float2(*(__half2*)&fhA.x);
            float2 a23 = __half22float2(*(__half2*)&fhA.y);
            float2 b01 = __half22float2(*(__half2*)&fhB.x);
            float2 b23 = __half22float2(*(__half2*)&fhB.y);
            acc.x = fmaf(wA, a01.x, fmaf(wB, b01.x, acc.x));
            acc.y = fmaf(wA, a01.y, fmaf(wB, b01.y, acc.y));
            acc.z = fmaf(wA, a23.x, fmaf(wB, b23.x, acc.z));
            acc.w = fmaf(wA, a23.y, fmaf(wB, b23.y, acc.w));
        }
        for (; j < pairs; ++j) {
            int idx = 2 * j + half;
            int sj = __shfl_sync(0xFFFFFFFFu, s, idx);
            float e0 = __shfl_sync(0xFFFFFFFFu, ex0, idx);
            float e1 = __shfl_sync(0xFFFFFFFFu, ex1, idx);
            float wgt = is_h0 ? e0 : e1;
            uint2 fh = *(const uint2*)&g_feat_h[sj * NHF + coff];
            float2 f01 = __half22float2(*(__half2*)&fh.x);
            float2 f23 = __half22float2(*(__half2*)&fh.y);
            acc.x = fmaf(wgt, f01.x, acc.x);
            acc.y = fmaf(wgt, f01.y, acc.y);
            acc.z = fmaf(wgt, f23.x, acc.z);
            acc.w = fmaf(wgt, f23.y, acc.w);
        }
    }

    // combine the two 16-lane halves (same columns, disjoint edge subsets)
    acc.x += __shfl_xor_sync(0xFFFFFFFFu, acc.x, 16);
    acc.y += __shfl_xor_sync(0xFFFFFFFFu, acc.y, 16);
    acc.z += __shfl_xor_sync(0xFFFFFFFFu, acc.z, 16);
    acc.w += __shfl_xor_sync(0xFFFFFFFFu, acc.w, 16);
    // full-warp denom reduce
    #pragma unroll
    for (int o = 1; o < 32; o <<= 1) {
        den0 += __shfl_xor_sync(0xFFFFFFFFu, den0, o);
        den1 += __shfl_xor_sync(0xFFFFFFFFu, den1, o);
    }
    float inv0 = (den0 > 0.f) ? 1.f / den0 : 0.f;
    float inv1 = (den1 > 0.f) ? 1.f / den1 : 0.f;
    float myinv = is_h0 ? inv0 : inv1;
    float r0 = acc.x * myinv, r1 = acc.y * myinv;
    float r2 = acc.z * myinv, r3 = acc.w * myinv;
    // head swap: lane li (0-7) holds head0 f=4li..4li+3; lane li+8 head1 same f
    float o0 = __shfl_xor_sync(0xFFFFFFFFu, r0, 8);
    float o1 = __shfl_xor_sync(0xFFFFFFFFu, r1, 8);
    float o2 = __shfl_xor_sync(0xFFFFFFFFu, r2, 8);
    float o3 = __shfl_xor_sync(0xFFFFFFFFu, r3, 8);
    float4 b0 = *(const float4*)&bias_gat[coff & 31];
    float4 b1 = *(const float4*)&bias_gat[32 + (coff & 31)];
    float h0 = fmaxf(0.5f * (r0 + o0 + b0.x + b1.x), 0.f);
    float h1 = fmaxf(0.5f * (r1 + o1 + b0.y + b1.y), 0.f);
    float h2 = fmaxf(0.5f * (r2 + o2 + b0.z + b1.z), 0.f);
    float h3 = fmaxf(0.5f * (r3 + o3 + b0.w + b1.w), 0.f);
    float4 va = *(const float4*)&g_vfold[coff & 31];
    float4 vb = *(const float4*)&g_vfold[32 + (coff & 31)];
    float av = h0 * va.x + h1 * va.y + h2 * va.z + h3 * va.w;
    float bv = h0 * vb.x + h1 * vb.y + h2 * vb.z + h3 * vb.w;
    // reduce within the 8-lane group (lanes 0-7 hold the real values)
    #pragma unroll
    for (int o = 1; o < 8; o <<= 1) {
        av += __shfl_xor_sync(0xFFFFFFFFu, av, o);
        bv += __shfl_xor_sync(0xFFFFFFFFu, bv, o);
    }
    if (lane == 0) { g_a[n] = av; g_b[n] = bv; }
}

// ---- per-edge final score (4 edges per thread) ----
__global__ void k_edge_score(const int* __restrict__ src, const int* __restrict__ dst,
                             float* __restrict__ out) {
    int i = blockIdx.x * blockDim.x + threadIdx.x;
    if (i * 4 >= N_EDGES) return;
    int4 s = *(const int4*)&src[i * 4];
    int4 d = *(const int4*)&dst[i * 4];
    float c = g_cfold;
    float4 r;
    r.x = g_a[s.x] + g_b[d.x] + c;
    r.y = g_a[s.y] + g_b[d.y] + c;
    r.z = g_a[s.z] + g_b[d.z] + c;
    r.w = g_a[s.w] + g_b[d.w] + c;
    *(float4*)&out[i * 4] = r;
}

extern "C" void kernel_launch(void* const* d_in, const int* in_sizes, int n_in,
                              void* d_out, int out_size) {
    const float* x       = (const float*)d_in[0];
    const float* W       = (const float*)d_in[1];
    const float* attn_l  = (const float*)d_in[2];
    const float* attn_r  = (const float*)d_in[3];
    const float* bias_gat= (const float*)d_in[4];
    const float* W1      = (const float*)d_in[5];
    const float* b1      = (const float*)d_in[6];
    const float* W2      = (const float*)d_in[7];
    const float* b2      = (const float*)d_in[8];
    const int*   src     = (const int*)d_in[9];
    const int*   dst     = (const int*)d_in[10];
    float* out = (float*)d_out;

    k_hist<<<(N_EDGES / 4 + 255) / 256, 256>>>(dst, W, attn_l, attn_r, W1, b1, W2, b2);
    k_scan1<<<N_SCAN_BLKS, SCAN_BLK>>>();
    k_scan3<<<N_SCAN_BLKS, SCAN_BLK>>>();
    k_gemm_mma<<<GEMM_GRID, 256>>>(x);
    k_scatter<<<(N_EDGES / 4 + 255) / 256, 256>>>(src, dst);
    k_agg<<<(N_NODES * 32 + 255) / 256, 256>>>(bias_gat);
    k_edge_score<<<(N_EDGES / 4 + 255) / 256, 256>>>(src, dst, out);
}